// round 1
// baseline (speedup 1.0000x reference)
#include <cuda_runtime.h>

// ContextEmbedding: B=256, S=512, D=256, NUM_CONTEXT=16
// token ids in [0, 76); special ids are [68, 76); CLS=68, CONTEXT=69.
//
// Inputs (metadata order):
//  0 token_ids        int32  [B,S]
//  1 context_features f32    [B,S,16]
//  2 special_table    f32    [8,256]
//  3 cls_w            f32    [3,256]
//  4 cls_b            f32    [256]
//  5 cls_ln_g         f32    [256]
//  6 cls_ln_b         f32    [256]
//  7 ctx_w            f32    [16,256]
//  8 ctx_b            f32    [256]
//  9 ctx_ln_g         f32    [256]
// 10 ctx_ln_b         f32    [256]
// Output: f32 [B,S,256]

#define D_MODEL        256
#define NUM_CONTEXT    16
#define SPECIAL_OFFSET 68
#define NUM_SPECIAL    8
#define LN_EPS         1e-5f

__global__ __launch_bounds__(256) void context_embedding_kernel(
    const int*   __restrict__ token_ids,
    const float* __restrict__ context_features,  // [T,16]
    const float* __restrict__ special_table,     // [8,256]
    const float* __restrict__ cls_w,             // [3,256]
    const float* __restrict__ cls_b,
    const float* __restrict__ cls_ln_g,
    const float* __restrict__ cls_ln_b,
    const float* __restrict__ ctx_w,             // [16,256]
    const float* __restrict__ ctx_b,
    const float* __restrict__ ctx_ln_g,
    const float* __restrict__ ctx_ln_b,
    float*       __restrict__ out,               // [T,256]
    int T)
{
    const int gwarp = (int)((blockIdx.x * blockDim.x + threadIdx.x) >> 5);
    const int lane  = threadIdx.x & 31;
    if (gwarp >= T) return;

    const int tok = token_ids[gwarp];

    float4* __restrict__ out4 = reinterpret_cast<float4*>(out + (size_t)gwarp * D_MODEL);

    // Fast path: non-special token -> zeros (89.5% of tokens)
    if (tok < SPECIAL_OFFSET || tok >= SPECIAL_OFFSET + NUM_SPECIAL) {
        const float4 z = make_float4(0.f, 0.f, 0.f, 0.f);
        out4[lane]      = z;
        out4[32 + lane] = z;
        return;
    }

    const int sid = tok - SPECIAL_OFFSET;

    // Gather embedding row (1 KB, L1/L2-resident)
    const float4* __restrict__ sp4 =
        reinterpret_cast<const float4*>(special_table + sid * D_MODEL);
    float4 e0 = sp4[lane];
    float4 e1 = sp4[32 + lane];

    // CLS (sid==0) or CONTEXT (sid==1): Linear -> LayerNorm -> ReLU, added on top
    if (sid <= 1) {
        const bool is_cls = (sid == 0);
        const int K = is_cls ? 3 : NUM_CONTEXT;
        const float* __restrict__ w  = is_cls ? cls_w    : ctx_w;
        const float* __restrict__ bi = is_cls ? cls_b    : ctx_b;
        const float* __restrict__ g  = is_cls ? cls_ln_g : ctx_ln_g;
        const float* __restrict__ bb = is_cls ? cls_ln_b : ctx_ln_b;

        const float* __restrict__ f = context_features + (size_t)gwarp * NUM_CONTEXT;

        // h = bias + sum_k f[k] * w[k, :]; lane owns 8 channels as two float4 groups
        const float4* bi4 = reinterpret_cast<const float4*>(bi);
        float4 a0 = bi4[lane];
        float4 a1 = bi4[32 + lane];
        float h[8] = {a0.x, a0.y, a0.z, a0.w, a1.x, a1.y, a1.z, a1.w};

        for (int k = 0; k < K; k++) {
            const float fk = f[k];  // same addr across lanes -> L1 broadcast
            const float4* w4 = reinterpret_cast<const float4*>(w + k * D_MODEL);
            const float4 w0 = w4[lane];
            const float4 w1 = w4[32 + lane];
            h[0] = fmaf(fk, w0.x, h[0]); h[1] = fmaf(fk, w0.y, h[1]);
            h[2] = fmaf(fk, w0.z, h[2]); h[3] = fmaf(fk, w0.w, h[3]);
            h[4] = fmaf(fk, w1.x, h[4]); h[5] = fmaf(fk, w1.y, h[5]);
            h[6] = fmaf(fk, w1.z, h[6]); h[7] = fmaf(fk, w1.w, h[7]);
        }

        // LayerNorm over D=256 via one-pass warp butterfly reduction
        float s = 0.f, s2 = 0.f;
        #pragma unroll
        for (int i = 0; i < 8; i++) { s += h[i]; s2 += h[i] * h[i]; }
        #pragma unroll
        for (int off = 16; off > 0; off >>= 1) {
            s  += __shfl_xor_sync(0xffffffffu, s,  off);
            s2 += __shfl_xor_sync(0xffffffffu, s2, off);
        }
        const float mu   = s * (1.0f / D_MODEL);
        const float var  = fmaxf(s2 * (1.0f / D_MODEL) - mu * mu, 0.f);
        const float rstd = rsqrtf(var + LN_EPS);

        const float4* g4  = reinterpret_cast<const float4*>(g);
        const float4* bb4 = reinterpret_cast<const float4*>(bb);
        const float4 g0 = g4[lane],      g1 = g4[32 + lane];
        const float4 b0 = bb4[lane],     b1 = bb4[32 + lane];

        e0.x += fmaxf((h[0] - mu) * rstd * g0.x + b0.x, 0.f);
        e0.y += fmaxf((h[1] - mu) * rstd * g0.y + b0.y, 0.f);
        e0.z += fmaxf((h[2] - mu) * rstd * g0.z + b0.z, 0.f);
        e0.w += fmaxf((h[3] - mu) * rstd * g0.w + b0.w, 0.f);
        e1.x += fmaxf((h[4] - mu) * rstd * g1.x + b1.x, 0.f);
        e1.y += fmaxf((h[5] - mu) * rstd * g1.y + b1.y, 0.f);
        e1.z += fmaxf((h[6] - mu) * rstd * g1.z + b1.z, 0.f);
        e1.w += fmaxf((h[7] - mu) * rstd * g1.w + b1.w, 0.f);
    }

    out4[lane]      = e0;
    out4[32 + lane] = e1;
}

extern "C" void kernel_launch(void* const* d_in, const int* in_sizes, int n_in,
                              void* d_out, int out_size)
{
    const int*   token_ids        = (const int*)  d_in[0];
    const float* context_features = (const float*)d_in[1];
    const float* special_table    = (const float*)d_in[2];
    const float* cls_w            = (const float*)d_in[3];
    const float* cls_b            = (const float*)d_in[4];
    const float* cls_ln_g         = (const float*)d_in[5];
    const float* cls_ln_b         = (const float*)d_in[6];
    const float* ctx_w            = (const float*)d_in[7];
    const float* ctx_b            = (const float*)d_in[8];
    const float* ctx_ln_g         = (const float*)d_in[9];
    const float* ctx_ln_b         = (const float*)d_in[10];
    float* out = (float*)d_out;

    const int T = in_sizes[0];               // B*S tokens
    const int warps_per_block = 256 / 32;    // 8 tokens per block
    const int blocks = (T + warps_per_block - 1) / warps_per_block;

    context_embedding_kernel<<<blocks, 256>>>(
        token_ids, context_features, special_table,
        cls_w, cls_b, cls_ln_g, cls_ln_b,
        ctx_w, ctx_b, ctx_ln_g, ctx_ln_b,
        out, T);
}

// round 2
// speedup vs baseline: 1.1649x; 1.1649x over previous
#include <cuda_runtime.h>

// ContextEmbedding: B=256, S=512, D=256. token ids in [0,76); special = [68,76);
// CLS=68, CONTEXT=69. Output f32 [B*S, 256] = 134 MB -> pure store-bound.
//
// Strategy: 32 tokens per warp. One coalesced LDG of 32 ids per warp, then a
// uniform loop over tokens (id broadcast via ballot/shfl). 89.5% of tokens are
// pure zero rows -> 2 independent STG.128 each; special rows gather a 1 KB
// L1-resident table row; CLS/CONTEXT (~2.6%) run a tiny GEMV + warp-LN + ReLU.
// Grid = T/256 = 512 blocks -> single wave on 148 SMs.

#define D_MODEL        256
#define NUM_CONTEXT    16
#define SPECIAL_OFFSET 68
#define NUM_SPECIAL    8
#define LN_EPS         1e-5f
#define FULL           0xffffffffu

__global__ __launch_bounds__(256) void context_embedding_kernel(
    const int*   __restrict__ token_ids,
    const float* __restrict__ context_features,  // [T,16]
    const float* __restrict__ special_table,     // [8,256]
    const float* __restrict__ cls_w,             // [3,256]
    const float* __restrict__ cls_b,
    const float* __restrict__ cls_ln_g,
    const float* __restrict__ cls_ln_b,
    const float* __restrict__ ctx_w,             // [16,256]
    const float* __restrict__ ctx_b,
    const float* __restrict__ ctx_ln_g,
    const float* __restrict__ ctx_ln_b,
    float*       __restrict__ out,               // [T,256]
    int T)
{
    const int warpId  = threadIdx.x >> 5;
    const int lane    = threadIdx.x & 31;
    const int tokBase = (blockIdx.x * 8 + warpId) * 32;   // 32 tokens per warp
    if (tokBase >= T) return;

    // One coalesced load of this warp's 32 token ids.
    const int myTok = token_ids[tokBase + lane];

    // Bitmask of lanes whose token is special / needs the LN branch.
    const bool isSpec = (myTok >= SPECIAL_OFFSET) && (myTok < SPECIAL_OFFSET + NUM_SPECIAL);
    const unsigned specMask = __ballot_sync(FULL, isSpec);
    const unsigned lnMask   = __ballot_sync(FULL, isSpec && (myTok <= SPECIAL_OFFSET + 1));

    const float4 z = make_float4(0.f, 0.f, 0.f, 0.f);

    #pragma unroll 4
    for (int t = 0; t < 32; t++) {
        float4* __restrict__ out4 =
            reinterpret_cast<float4*>(out + (size_t)(tokBase + t) * D_MODEL);

        if (!((specMask >> t) & 1u)) {
            // Zero row: two independent streaming STG.128 per lane.
            __stcs(&out4[lane],      z);
            __stcs(&out4[32 + lane], z);
            continue;
        }

        const int tok = __shfl_sync(FULL, myTok, t);
        const int sid = tok - SPECIAL_OFFSET;

        const float4* __restrict__ sp4 =
            reinterpret_cast<const float4*>(special_table + sid * D_MODEL);
        float4 e0 = sp4[lane];
        float4 e1 = sp4[32 + lane];

        if ((lnMask >> t) & 1u) {
            const bool is_cls = (sid == 0);
            const int K = is_cls ? 3 : NUM_CONTEXT;
            const float* __restrict__ w  = is_cls ? cls_w    : ctx_w;
            const float* __restrict__ bi = is_cls ? cls_b    : ctx_b;
            const float* __restrict__ g  = is_cls ? cls_ln_g : ctx_ln_g;
            const float* __restrict__ bb = is_cls ? cls_ln_b : ctx_ln_b;

            const float* __restrict__ f =
                context_features + (size_t)(tokBase + t) * NUM_CONTEXT;

            const float4* bi4 = reinterpret_cast<const float4*>(bi);
            const float4 a0 = bi4[lane];
            const float4 a1 = bi4[32 + lane];
            float h[8] = {a0.x, a0.y, a0.z, a0.w, a1.x, a1.y, a1.z, a1.w};

            for (int k = 0; k < K; k++) {
                const float fk = f[k];  // uniform address -> broadcast
                const float4* w4 = reinterpret_cast<const float4*>(w + k * D_MODEL);
                const float4 w0 = w4[lane];
                const float4 w1 = w4[32 + lane];
                h[0] = fmaf(fk, w0.x, h[0]); h[1] = fmaf(fk, w0.y, h[1]);
                h[2] = fmaf(fk, w0.z, h[2]); h[3] = fmaf(fk, w0.w, h[3]);
                h[4] = fmaf(fk, w1.x, h[4]); h[5] = fmaf(fk, w1.y, h[5]);
                h[6] = fmaf(fk, w1.z, h[6]); h[7] = fmaf(fk, w1.w, h[7]);
            }

            // LayerNorm over D=256: one-pass warp butterfly reduction.
            float s = 0.f, s2 = 0.f;
            #pragma unroll
            for (int i = 0; i < 8; i++) { s += h[i]; s2 += h[i] * h[i]; }
            #pragma unroll
            for (int off = 16; off > 0; off >>= 1) {
                s  += __shfl_xor_sync(FULL, s,  off);
                s2 += __shfl_xor_sync(FULL, s2, off);
            }
            const float mu   = s * (1.0f / D_MODEL);
            const float var  = fmaxf(s2 * (1.0f / D_MODEL) - mu * mu, 0.f);
            const float rstd = rsqrtf(var + LN_EPS);

            const float4* g4  = reinterpret_cast<const float4*>(g);
            const float4* bb4 = reinterpret_cast<const float4*>(bb);
            const float4 g0 = g4[lane],  g1 = g4[32 + lane];
            const float4 b0 = bb4[lane], b1 = bb4[32 + lane];

            e0.x += fmaxf((h[0] - mu) * rstd * g0.x + b0.x, 0.f);
            e0.y += fmaxf((h[1] - mu) * rstd * g0.y + b0.y, 0.f);
            e0.z += fmaxf((h[2] - mu) * rstd * g0.z + b0.z, 0.f);
            e0.w += fmaxf((h[3] - mu) * rstd * g0.w + b0.w, 0.f);
            e1.x += fmaxf((h[4] - mu) * rstd * g1.x + b1.x, 0.f);
            e1.y += fmaxf((h[5] - mu) * rstd * g1.y + b1.y, 0.f);
            e1.z += fmaxf((h[6] - mu) * rstd * g1.z + b1.z, 0.f);
            e1.w += fmaxf((h[7] - mu) * rstd * g1.w + b1.w, 0.f);
        }

        __stcs(&out4[lane],      e0);
        __stcs(&out4[32 + lane], e1);
    }
}

extern "C" void kernel_launch(void* const* d_in, const int* in_sizes, int n_in,
                              void* d_out, int out_size)
{
    const int*   token_ids        = (const int*)  d_in[0];
    const float* context_features = (const float*)d_in[1];
    const float* special_table    = (const float*)d_in[2];
    const float* cls_w            = (const float*)d_in[3];
    const float* cls_b            = (const float*)d_in[4];
    const float* cls_ln_g         = (const float*)d_in[5];
    const float* cls_ln_b         = (const float*)d_in[6];
    const float* ctx_w            = (const float*)d_in[7];
    const float* ctx_b            = (const float*)d_in[8];
    const float* ctx_ln_g         = (const float*)d_in[9];
    const float* ctx_ln_b         = (const float*)d_in[10];
    float* out = (float*)d_out;

    const int T = in_sizes[0];                    // B*S tokens
    const int tokens_per_block = 8 * 32;          // 8 warps x 32 tokens
    const int blocks = (T + tokens_per_block - 1) / tokens_per_block;  // 512

    context_embedding_kernel<<<blocks, 256>>>(
        token_ids, context_features, special_table,
        cls_w, cls_b, cls_ln_g, cls_ln_b,
        ctx_w, ctx_b, ctx_ln_g, ctx_ln_b,
        out, T);
}